// round 10
// baseline (speedup 1.0000x reference)
#include <cuda_runtime.h>

#define Bb 16
#define Nn 512
#define Tt 24
#define Dd 64
#define Ee 64
#define Hh 64
#define ESTR 132   // transposed-buffer row stride (128 + 4 pad)

// E2 scratch, k-major [B,T,E,N]
__device__ float g_e2t[Bb * Tt * Ee * Nn];

typedef unsigned long long ull;

// ---------- helpers ----------
__device__ __forceinline__ ull dup2(float a) {
    ull r;
    asm("mov.b64 %0, {%1, %1};" : "=l"(r) : "f"(a));
    return r;
}
__device__ __forceinline__ void fma2(ull& c, ull a, ull b) {
    asm("fma.rn.f32x2 %0, %1, %2, %0;" : "+l"(c) : "l"(a), "l"(b));
}
__device__ __forceinline__ float2 unpk(ull v) {
    float2 r;
    asm("mov.b64 {%0, %1}, %2;" : "=f"(r.x), "=f"(r.y) : "l"(v));
    return r;
}
__device__ __forceinline__ void cp16(float* s, const float* g) {
    unsigned int sa = (unsigned int)__cvta_generic_to_shared(s);
    asm volatile("cp.async.cg.shared.global [%0], [%1], 16;" ::"r"(sa), "l"(g));
}
__device__ __forceinline__ void cp_commit() { asm volatile("cp.async.commit_group;"); }
template <int N>
__device__ __forceinline__ void cp_wait() {
    asm volatile("cp.async.wait_group %0;" ::"n"(N));
}

// 32 fma2: acc[p][v] += a-pair p * dup(b col v); pairs cover rows 2p,2p+1 (16 rows)
__device__ __forceinline__ void mma16(ull (*acc)[4], const float* a_t, int astride,
                                      const float* bm, int k, int r0, int c0) {
    ulonglong2 a01 = *(const ulonglong2*)&a_t[k * astride + r0];
    ulonglong2 a23 = *(const ulonglong2*)&a_t[k * astride + r0 + 4];
    ulonglong2 a45 = *(const ulonglong2*)&a_t[k * astride + r0 + 8];
    ulonglong2 a67 = *(const ulonglong2*)&a_t[k * astride + r0 + 12];
    float4 bq = *(const float4*)&bm[k * 64 + c0];
    ull b0 = dup2(bq.x), b1 = dup2(bq.y), b2 = dup2(bq.z), b3 = dup2(bq.w);
    fma2(acc[0][0], a01.x, b0); fma2(acc[0][1], a01.x, b1);
    fma2(acc[0][2], a01.x, b2); fma2(acc[0][3], a01.x, b3);
    fma2(acc[1][0], a01.y, b0); fma2(acc[1][1], a01.y, b1);
    fma2(acc[1][2], a01.y, b2); fma2(acc[1][3], a01.y, b3);
    fma2(acc[2][0], a23.x, b0); fma2(acc[2][1], a23.x, b1);
    fma2(acc[2][2], a23.x, b2); fma2(acc[2][3], a23.x, b3);
    fma2(acc[3][0], a23.y, b0); fma2(acc[3][1], a23.y, b1);
    fma2(acc[3][2], a23.y, b2); fma2(acc[3][3], a23.y, b3);
    fma2(acc[4][0], a45.x, b0); fma2(acc[4][1], a45.x, b1);
    fma2(acc[4][2], a45.x, b2); fma2(acc[4][3], a45.x, b3);
    fma2(acc[5][0], a45.y, b0); fma2(acc[5][1], a45.y, b1);
    fma2(acc[5][2], a45.y, b2); fma2(acc[5][3], a45.y, b3);
    fma2(acc[6][0], a67.x, b0); fma2(acc[6][1], a67.x, b1);
    fma2(acc[6][2], a67.x, b2); fma2(acc[6][3], a67.x, b3);
    fma2(acc[7][0], a67.y, b0); fma2(acc[7][1], a67.y, b1);
    fma2(acc[7][2], a67.y, b2); fma2(acc[7][3], a67.y, b3);
}

// unpack pair-accs acc[8][4] -> pv[16][4]
__device__ __forceinline__ void unpack16(const ull (*acc)[4], float (*pv)[4]) {
#pragma unroll
    for (int p = 0; p < 8; p++)
#pragma unroll
        for (int v = 0; v < 4; v++) {
            float2 f = unpk(acc[p][v]);
            pv[2 * p][v] = f.x;
            pv[2 * p + 1][v] = f.y;
        }
}

// store pv[16][4] transposed: base[(c0+v)*stride + r0 + 4q]
__device__ __forceinline__ void store_t16(float* base, int c0, int r0,
                                          const float (*pv)[4], int stride) {
#pragma unroll
    for (int v = 0; v < 4; v++)
#pragma unroll
        for (int q = 0; q < 4; q++)
            *(float4*)&base[(c0 + v) * stride + r0 + 4 * q] =
                make_float4(pv[4 * q][v], pv[4 * q + 1][v],
                            pv[4 * q + 2][v], pv[4 * q + 3][v]);
}

// unpack col-pair accs acc[16][2] -> pv[16][4]
__device__ __forceinline__ void unpack162(const ull (*acc)[2], float (*pv)[4]) {
#pragma unroll
    for (int u = 0; u < 16; u++) {
        float2 p0 = unpk(acc[u][0]), p1 = unpk(acc[u][1]);
        pv[u][0] = p0.x; pv[u][1] = p0.y; pv[u][2] = p1.x; pv[u][3] = p1.y;
    }
}

// ============================================================================
// Kernel P: E2^T = (x@W2+b2)^T stored k-major [B,T,E,N].
// grid = B*T*8, 128 threads, 8x4 thread tile. (unchanged, ~40us)
// ============================================================================
__global__ void __launch_bounds__(128, 4)
gcn_proj(const float* __restrict__ x, const float* __restrict__ W2,
         const float* __restrict__ b2) {
    extern __shared__ float sm[];
    float* xb = sm;          // 4096
    float* Ws = sm + 4096;   // 4096
    float* bs = sm + 8192;   // 64

    const int tid = threadIdx.x;
    const int blk = blockIdx.x;
    const int nt = blk & 7, bt = blk >> 3;
    const int t = bt % Tt, b = bt / Tt;
    const int n0 = nt * 64;
    const float* xg = x + ((size_t)(b * Nn + n0) * Tt + t) * Dd;

#pragma unroll
    for (int i = 0; i < 8; i++) {
        int ch = tid + 128 * i, row = ch >> 4, col = (ch & 15) * 4;
        cp16(&xb[row * 64 + col], &xg[(size_t)row * (Tt * Dd) + col]);
        cp16(&Ws[ch * 4], &W2[ch * 4]);
    }
    if (tid < 16) cp16(&bs[tid * 4], &b2[tid * 4]);
    cp_commit();
    cp_wait<0>();
    __syncthreads();

    const int r0 = (tid >> 4) * 8, c0 = (tid & 15) * 4;
    ull acc[8][2];
    {
        ulonglong2 bb = *(const ulonglong2*)&bs[c0];
#pragma unroll
        for (int u = 0; u < 8; u++) { acc[u][0] = bb.x; acc[u][1] = bb.y; }
    }
#pragma unroll 8
    for (int d = 0; d < 64; d++) {
        ulonglong2 wv = *(const ulonglong2*)&Ws[d * 64 + c0];
#pragma unroll
        for (int u = 0; u < 8; u++) {
            ull ad = dup2(xb[(r0 + u) * 64 + d]);
            fma2(acc[u][0], ad, wv.x);
            fma2(acc[u][1], ad, wv.y);
        }
    }
    float pv[8][4];
#pragma unroll
    for (int u = 0; u < 8; u++) {
        float2 p0 = unpk(acc[u][0]), p1 = unpk(acc[u][1]);
        pv[u][0] = p0.x; pv[u][1] = p0.y; pv[u][2] = p1.x; pv[u][3] = p1.y;
    }
    float* gout = g_e2t + (size_t)(b * Tt + t) * Ee * Nn + n0;
#pragma unroll
    for (int v = 0; v < 4; v++) {
        *(float4*)&gout[(size_t)(c0 + v) * Nn + r0] =
            make_float4(pv[0][v], pv[1][v], pv[2][v], pv[3][v]);
        *(float4*)&gout[(size_t)(c0 + v) * Nn + r0 + 4] =
            make_float4(pv[4][v], pv[5][v], pv[6][v], pv[7][v]);
    }
}

// ============================================================================
// Kernel M: per (b,t,i-tile of 128): E1=x_i@W1+b1; stream 8 j-tiles:
//   S=E1 E2^T, P=exp(relu(S)), H += P X; out = relu((H/rs) W + b)
// grid = B*T*4, 128 threads (16x4 per-thread tile), 2 CTAs/SM, 256-reg budget.
// ============================================================================
__global__ void __launch_bounds__(128, 2)
gcn_main(const float* __restrict__ x, const float* __restrict__ W1,
         const float* __restrict__ b1, const float* __restrict__ W,
         const float* __restrict__ bias, float* __restrict__ out) {
    extern __shared__ float sm[];
    float* e1s   = sm;           // 8448  E1^T [e][i] stride 132
    float* Pt    = sm + 8448;    // 8448  P^T/H^T [j|d][i] stride 132 (also x_i staging)
    float* eb    = sm + 16896;   // 4096  e2 tile [e][j] (also W1 staging, W in ph4)
    float* xb    = sm + 20992;   // 4096  x tile [j][d]
    float* bs1   = sm + 25088;   // 64
    float* bsO   = sm + 25152;   // 64
    float* rpart = sm + 25216;   // 256  row-sum partials [warpC][row 0..127]
                                 // total 25472 floats = 101,888 B

    const int tid = threadIdx.x;
    const int blk = blockIdx.x;
    const int it = blk & 3, bt = blk >> 2;
    const int t = bt % Tt, b = bt / Tt;
    const int i0 = it * 128;

    const float* e2g = g_e2t + (size_t)(b * Tt + t) * Ee * Nn;
    const float* xg = x + ((size_t)b * Nn * Tt + t) * Dd;

    const int warp = tid >> 5, lane = tid & 31;
    const int wC = warp & 1;
    const int r0 = (warp >> 1) * 64 + (lane >> 3) * 16;  // 0..112
    const int c0 = wC * 32 + (lane & 7) * 4;             // 0..60

    // ---- prologue: x_i (128 rows) -> Pt (stride 64), W1 -> eb, biases ----
#pragma unroll
    for (int i = 0; i < 16; i++) {
        int ch = tid + 128 * i, row = ch >> 4, col = (ch & 15) * 4;
        cp16(&Pt[row * 64 + col], &xg[(size_t)(i0 + row) * (Tt * Dd) + col]);
    }
#pragma unroll
    for (int i = 0; i < 8; i++) {
        int ch = tid + 128 * i;
        cp16(&eb[ch * 4], &W1[ch * 4]);
    }
    if (tid < 16) cp16(&bs1[tid * 4], &b1[tid * 4]);
    else if (tid < 32) cp16(&bsO[(tid - 16) * 4], &bias[(tid - 16) * 4]);
    cp_commit();
    cp_wait<0>();
    __syncthreads();

    // ---- GEMM0: E1 = x_i @ W1 + b1 -> e1s transposed (dup-a style) ----
    {
        const int r0g = (tid >> 4) * 16;   // 0..112
        const int c0g = (tid & 15) * 4;    // 0..60
        ull a0[16][2];
        ulonglong2 bb = *(const ulonglong2*)&bs1[c0g];
#pragma unroll
        for (int u = 0; u < 16; u++) { a0[u][0] = bb.x; a0[u][1] = bb.y; }
#pragma unroll 4
        for (int d = 0; d < 64; d++) {
            ulonglong2 wv = *(const ulonglong2*)&eb[d * 64 + c0g];
#pragma unroll
            for (int u = 0; u < 16; u++) {
                ull ad = dup2(Pt[(r0g + u) * 64 + d]);
                fma2(a0[u][0], ad, wv.x);
                fma2(a0[u][1], ad, wv.y);
            }
        }
        float pv[16][4];
        unpack162(a0, pv);
        __syncthreads();  // all x_i/W1 reads done before e1s write? (e1s separate;
                          // this sync orders Pt reuse below instead)
        store_t16(e1s, c0g, r0g, pv, ESTR);
    }
    __syncthreads();  // e1s visible; Pt/eb free

    // kick off pipeline: e2(0) then x(0) as separate groups
#pragma unroll
    for (int i = 0; i < 8; i++) {
        int ch = tid + 128 * i, row = ch >> 4, col = (ch & 15) * 4;
        cp16(&eb[row * 64 + col], &e2g[row * Nn + col]);
    }
    cp_commit();
#pragma unroll
    for (int i = 0; i < 8; i++) {
        int ch = tid + 128 * i, row = ch >> 4, col = (ch & 15) * 4;
        cp16(&xb[row * 64 + col], &xg[(size_t)row * (Tt * Dd) + col]);
    }
    cp_commit();

    float rsp[16];
#pragma unroll
    for (int u = 0; u < 16; u++) rsp[u] = 0.f;
    ull acc3[8][4];
#pragma unroll
    for (int p = 0; p < 8; p++)
#pragma unroll
        for (int v = 0; v < 4; v++) acc3[p][v] = 0ull;

    for (int jt = 0; jt < 8; jt++) {
        cp_wait<1>();  // e2(jt) ready
        __syncthreads();

        // ---- GEMM1: S-tile = E1 E2^T (pair-packed rows) ----
        ull acc[8][4];
#pragma unroll
        for (int p = 0; p < 8; p++)
#pragma unroll
            for (int v = 0; v < 4; v++) acc[p][v] = 0ull;
#pragma unroll 4
        for (int e = 0; e < 64; e++) mma16(acc, e1s, ESTR, eb, e, r0, c0);

        // ---- exp(relu) max-free, partial row sums, P^T store ----
        float pv[16][4];
        unpack16(acc, pv);
#pragma unroll
        for (int u = 0; u < 16; u++) {
#pragma unroll
            for (int v = 0; v < 4; v++)
                pv[u][v] = __expf(fmaxf(pv[u][v], 0.f));
            rsp[u] += (pv[u][0] + pv[u][1]) + (pv[u][2] + pv[u][3]);
        }
        store_t16(Pt, c0, r0, pv, ESTR);
        __syncthreads();  // Pt complete; eb free

        // prefetch next e2 (or W on last iter) into eb
        if (jt < 7) {
            const float* src = e2g + (jt + 1) * 64;
#pragma unroll
            for (int i = 0; i < 8; i++) {
                int ch = tid + 128 * i, row = ch >> 4, col = (ch & 15) * 4;
                cp16(&eb[row * 64 + col], &src[row * Nn + col]);
            }
        } else {
#pragma unroll
            for (int i = 0; i < 8; i++) {
                int ch = tid + 128 * i;
                cp16(&eb[ch * 4], &W[ch * 4]);
            }
        }
        cp_commit();
        cp_wait<1>();  // x(jt) ready
        __syncthreads();

        // ---- GEMM2: H += P X ----
#pragma unroll 4
        for (int j = 0; j < 64; j++) mma16(acc3, Pt, ESTR, xb, j, r0, c0);
        __syncthreads();  // xb free

        if (jt < 7) {
            const float* src = xg + (size_t)(jt + 1) * 64 * (Tt * Dd);
#pragma unroll
            for (int i = 0; i < 8; i++) {
                int ch = tid + 128 * i, row = ch >> 4, col = (ch & 15) * 4;
                cp16(&xb[row * 64 + col], &src[(size_t)row * (Tt * Dd) + col]);
            }
            cp_commit();
        }
    }

    // ---- finalize row sums: 8-lane butterfly, then cross-warpC combine ----
#pragma unroll
    for (int u = 0; u < 16; u++) {
#pragma unroll
        for (int o = 1; o < 8; o <<= 1)
            rsp[u] += __shfl_xor_sync(0xffffffffu, rsp[u], o);
    }
    if ((lane & 7) == 0) {
#pragma unroll
        for (int u = 0; u < 16; u++) rpart[wC * 128 + r0 + u] = rsp[u];
    }
    __syncthreads();

    // ---- H normalized -> Pt transposed (H^T [d][i]) ----
    {
        float hv[16][4];
        unpack16(acc3, hv);
#pragma unroll
        for (int u = 0; u < 16; u++) {
            float inv = 1.f / (rpart[r0 + u] + rpart[128 + r0 + u]);
#pragma unroll
            for (int v = 0; v < 4; v++) hv[u][v] *= inv;
        }
        store_t16(Pt, c0, r0, hv, ESTR);
    }
    cp_wait<0>();  // W in eb
    __syncthreads();

    // ---- GEMM3: out = relu(H W + b) ----
    ull a4[8][4];
    {
#pragma unroll
        for (int v = 0; v < 4; v++) {
            ull bv = dup2(bsO[c0 + v]);
#pragma unroll
            for (int p = 0; p < 8; p++) a4[p][v] = bv;
        }
    }
#pragma unroll 4
    for (int d = 0; d < 64; d++) mma16(a4, Pt, ESTR, eb, d, r0, c0);

    float ov[16][4];
    unpack16(a4, ov);
#pragma unroll
    for (int u = 0; u < 16; u++) {
        float4 o = make_float4(fmaxf(ov[u][0], 0.f), fmaxf(ov[u][1], 0.f),
                               fmaxf(ov[u][2], 0.f), fmaxf(ov[u][3], 0.f));
        *(float4*)&out[((size_t)(b * Nn + i0 + r0 + u) * Tt + t) * Hh + c0] = o;
    }
}

// ============================================================================
extern "C" void kernel_launch(void* const* d_in, const int* in_sizes, int n_in,
                              void* d_out, int out_size) {
    const float* x  = (const float*)d_in[0];
    const float* W1 = (const float*)d_in[1];
    const float* b1 = (const float*)d_in[2];
    const float* W2 = (const float*)d_in[3];
    const float* b2 = (const float*)d_in[4];
    const float* W  = (const float*)d_in[5];
    const float* bias = (const float*)d_in[6];
    float* out = (float*)d_out;

    const int smemP = 8256 * 4;    // 33,024 B
    const int smemM = 25472 * 4;   // 101,888 B
    cudaFuncSetAttribute(gcn_proj, cudaFuncAttributeMaxDynamicSharedMemorySize, smemP);
    cudaFuncSetAttribute(gcn_main, cudaFuncAttributeMaxDynamicSharedMemorySize, smemM);

    gcn_proj<<<Bb * Tt * 8, 128, smemP>>>(x, W2, b2);
    gcn_main<<<Bb * Tt * 4, 128, smemM>>>(x, W1, b1, W, bias, out);
}

// round 12
// speedup vs baseline: 2.0725x; 2.0725x over previous
#include <cuda_runtime.h>
#include <cstdint>

#define Bb 16
#define Nn 512
#define Tt 24
#define Dd 64
#define Ee 64
#define Hh 64

typedef unsigned long long ull;
typedef unsigned int u32;

// bf16 hi/lo operand planes, row-major 64x64 tiles (128B rows): [(b*Tt+t)*8 + jt]
__device__ __align__(128) unsigned char g_e2h[(size_t)Bb * Tt * Nn * 128];
__device__ __align__(128) unsigned char g_e2l[(size_t)Bb * Tt * Nn * 128];
__device__ __align__(128) unsigned char g_xth[(size_t)Bb * Tt * Dd * 1024];
__device__ __align__(128) unsigned char g_xtl[(size_t)Bb * Tt * Dd * 1024];

// ---------- SIMT helpers ----------
__device__ __forceinline__ ull dup2(float a) {
    ull r; asm("mov.b64 %0, {%1, %1};" : "=l"(r) : "f"(a)); return r;
}
__device__ __forceinline__ void fma2(ull& c, ull a, ull b) {
    asm("fma.rn.f32x2 %0, %1, %2, %0;" : "+l"(c) : "l"(a), "l"(b));
}
__device__ __forceinline__ float2 unpk(ull v) {
    float2 r; asm("mov.b64 {%0, %1}, %2;" : "=f"(r.x), "=f"(r.y) : "l"(v)); return r;
}
__device__ __forceinline__ void cp16(void* s, const void* g) {
    u32 sa = (u32)__cvta_generic_to_shared(s);
    asm volatile("cp.async.cg.shared.global [%0], [%1], 16;" ::"r"(sa), "l"(g));
}
__device__ __forceinline__ void cp16s(u32 sa, const void* g) {
    asm volatile("cp.async.cg.shared.global [%0], [%1], 16;" ::"r"(sa), "l"(g));
}
__device__ __forceinline__ void cp_commit() { asm volatile("cp.async.commit_group;"); }
template <int N> __device__ __forceinline__ void cp_wait() {
    asm volatile("cp.async.wait_group %0;" ::"n"(N));
}
// split (v0,v1) -> bf16x2 hi (v0 in low half) + bf16x2 lo residual
__device__ __forceinline__ void split2(float v0, float v1, u32& h, u32& l) {
    u32 hp;
    asm("cvt.rn.satfinite.bf16x2.f32 %0, %1, %2;" : "=r"(hp) : "f"(v1), "f"(v0));
    float h0 = __uint_as_float(hp << 16);
    float h1 = __uint_as_float(hp & 0xffff0000u);
    float l0 = v0 - h0, l1 = v1 - h1;
    asm("cvt.rn.satfinite.bf16x2.f32 %0, %1, %2;" : "=r"(l) : "f"(l1), "f"(l0));
    h = hp;
}

// ---------- tensor-core (warp mma) helpers ----------
__device__ __forceinline__ void ldm4(u32 addr, u32& r0, u32& r1, u32& r2, u32& r3) {
    asm volatile("ldmatrix.sync.aligned.m8n8.x4.shared.b16 {%0,%1,%2,%3}, [%4];"
                 : "=r"(r0), "=r"(r1), "=r"(r2), "=r"(r3) : "r"(addr));
}
__device__ __forceinline__ void mmab(float* d, const u32* a, u32 b0, u32 b1) {
    asm volatile(
        "mma.sync.aligned.m16n8k16.row.col.f32.bf16.bf16.f32 "
        "{%0,%1,%2,%3},{%4,%5,%6,%7},{%8,%9},{%0,%1,%2,%3};"
        : "+f"(d[0]), "+f"(d[1]), "+f"(d[2]), "+f"(d[3])
        : "r"(a[0]), "r"(a[1]), "r"(a[2]), "r"(a[3]), "r"(b0), "r"(b1));
}
// copy 8KB gmem plane (64 rows x 128B) into smem rows of stride 144B
__device__ __forceinline__ void cp_tile(u32 dst, const unsigned char* src, int tid) {
#pragma unroll
    for (int i = 0; i < 4; i++) {
        int ch = tid + 128 * i;  // 0..511
        u32 row = (u32)(ch >> 3), c16 = (u32)(ch & 7);
        cp16s(dst + row * 144 + c16 * 16, src + (size_t)ch * 16);
    }
}

// ============================================================================
// Kernel P: E2 = x@W2+b2 -> bf16 hi/lo tiles [j][e]; X^T tiles [d][j] hi/lo.
// grid = B*T*8 (j-tile 64), 128 threads.
// ============================================================================
__global__ void __launch_bounds__(128, 4)
gcn_proj(const float* __restrict__ x, const float* __restrict__ W2,
         const float* __restrict__ b2) {
    extern __shared__ float sm[];
    float* xb = sm;          // [64][68] x tile (stride 68 vs column-read conflicts)
    float* Ws = sm + 4352;   // [64][64] W2
    float* bs = sm + 8448;   // 64

    const int tid = threadIdx.x;
    const int blk = blockIdx.x;
    const int nt = blk & 7, bt = blk >> 3;
    const int t = bt % Tt, b = bt / Tt;
    const int n0 = nt * 64;
    const float* xg = x + ((size_t)(b * Nn + n0) * Tt + t) * Dd;
    const size_t tile = (size_t)(b * Tt + t) * 8 + nt;

#pragma unroll
    for (int i = 0; i < 8; i++) {
        int ch = tid + 128 * i, row = ch >> 4, c16 = ch & 15;
        cp16(&xb[row * 68 + c16 * 4], &xg[(size_t)row * (Tt * Dd) + c16 * 4]);
        cp16(&Ws[ch * 4], &W2[ch * 4]);
    }
    if (tid < 16) cp16(&bs[tid * 4], &b2[tid * 4]);
    cp_commit();
    cp_wait<0>();
    __syncthreads();

    const int r0 = (tid >> 4) * 8, c0 = (tid & 15) * 4;
    ull acc[8][2];
    {
        ulonglong2 bb = *(const ulonglong2*)&bs[c0];
#pragma unroll
        for (int u = 0; u < 8; u++) { acc[u][0] = bb.x; acc[u][1] = bb.y; }
    }
#pragma unroll 8
    for (int d = 0; d < 64; d++) {
        ulonglong2 wv = *(const ulonglong2*)&Ws[d * 64 + c0];
#pragma unroll
        for (int u = 0; u < 8; u++) {
            ull ad = dup2(xb[(r0 + u) * 68 + d]);
            fma2(acc[u][0], ad, wv.x);
            fma2(acc[u][1], ad, wv.y);
        }
    }
    // E2 tile [j][e] bf16 hi/lo (128B rows)
    unsigned char* e2h = g_e2h + tile * 8192;
    unsigned char* e2l = g_e2l + tile * 8192;
#pragma unroll
    for (int u = 0; u < 8; u++) {
        float2 p0 = unpk(acc[u][0]), p1 = unpk(acc[u][1]);
        u32 h0, l0, h1, l1;
        split2(p0.x, p0.y, h0, l0);
        split2(p1.x, p1.y, h1, l1);
        u32 off = (u32)(r0 + u) * 128 + (u32)c0 * 2;
        *(uint2*)(e2h + off) = make_uint2(h0, h1);
        *(uint2*)(e2l + off) = make_uint2(l0, l1);
    }
    // X^T tile [d][j] bf16 hi/lo
    {
        const int dd = tid >> 1, jh = (tid & 1) * 32;
        u32 hi[16], lo[16];
#pragma unroll
        for (int c = 0; c < 16; c++) {
            float v0 = xb[(jh + 2 * c) * 68 + dd];
            float v1 = xb[(jh + 2 * c + 1) * 68 + dd];
            split2(v0, v1, hi[c], lo[c]);
        }
        unsigned char* xth = g_xth + tile * 8192;
        unsigned char* xtl = g_xtl + tile * 8192;
        u32 base = (u32)dd * 128 + (u32)jh * 2;
#pragma unroll
        for (int c4 = 0; c4 < 4; c4++) {
            *(uint4*)(xth + base + 16 * c4) = *(uint4*)&hi[4 * c4];
            *(uint4*)(xtl + base + 16 * c4) = *(uint4*)&lo[4 * c4];
        }
    }
}

// ============================================================================
// Kernel M: mma.sync main. grid = B*T*8 (i-tile 64), 128 threads, 2 CTAs/SM.
// smem bytes: E1H 0 (9216), E1L 9216, E2 bufs 18432+q*18432 (hi+0, lo+9216),
//   XT bufs 55296+q*18432, bs1 92160, bsO 92416. total 92672.
// GEMM0 staging: x_i fp32 -> E2 buf0, W1 fp32 -> E2 buf1 (before pipeline).
// W fp32 staged in XT buf0 at jt==6; W^T planes built in E2 buf0 after loop.
// ============================================================================
__global__ void __launch_bounds__(128, 2)
gcn_main(const float* __restrict__ x, const float* __restrict__ W1,
         const float* __restrict__ b1, const float* __restrict__ W,
         const float* __restrict__ bias, float* __restrict__ out) {
    extern __shared__ unsigned char SB[];
    const u32 sb = (u32)__cvta_generic_to_shared(SB);
    const u32 E1H = 0, E1L = 9216, E2B = 18432, XTB = 55296;
    const u32 BS1 = 92160, BSO = 92416;

    const int tid = threadIdx.x, w = tid >> 5, l = tid & 31;
    const int blk = blockIdx.x;
    const int it = blk & 7, bt = blk >> 3;
    const int t = bt % Tt, b = bt / Tt;
    const int i0 = it * 64;
    const size_t tb = (size_t)(b * Tt + t) * 8;
    const float* xg = x + ((size_t)b * Nn * Tt + t) * Dd;

    // ---- g0: x_i fp32 -> E2 buf0, W1 fp32 -> E2 buf1, biases ----
    {
        float* xi = (float*)(SB + E2B);
        float* W1s = (float*)(SB + E2B + 18432);
#pragma unroll
        for (int i = 0; i < 8; i++) {
            int ch = tid + 128 * i, row = ch >> 4, c16 = ch & 15;
            cp16(&xi[row * 64 + c16 * 4], &xg[(size_t)(i0 + row) * (Tt * Dd) + c16 * 4]);
            cp16(&W1s[ch * 4], &W1[ch * 4]);
        }
        if (tid < 16) cp16((float*)(SB + BS1) + tid * 4, b1 + tid * 4);
        else if (tid < 32) cp16((float*)(SB + BSO) + (tid - 16) * 4, bias + (tid - 16) * 4);
        cp_commit();
    }
    // g1: XT(0), g2: XT(1)
    cp_tile(sb + XTB, g_xth + tb * 8192, tid);
    cp_tile(sb + XTB + 9216, g_xtl + tb * 8192, tid);
    cp_commit();
    cp_tile(sb + XTB + 18432, g_xth + (tb + 1) * 8192, tid);
    cp_tile(sb + XTB + 18432 + 9216, g_xtl + (tb + 1) * 8192, tid);
    cp_commit();
    cp_wait<2>();
    __syncthreads();

    // ---- GEMM0 (SIMT): E1 = x_i @ W1 + b1 -> bf16 planes stride 144 ----
    {
        const float* xi = (const float*)(SB + E2B);
        const float* W1s = (const float*)(SB + E2B + 18432);
        const float* bs1 = (const float*)(SB + BS1);
        const int r0 = (tid >> 4) * 8, c0 = (tid & 15) * 4;
        ull a0[8][2];
        ulonglong2 bb = *(const ulonglong2*)&bs1[c0];
#pragma unroll
        for (int u = 0; u < 8; u++) { a0[u][0] = bb.x; a0[u][1] = bb.y; }
#pragma unroll 8
        for (int d = 0; d < 64; d++) {
            ulonglong2 wv = *(const ulonglong2*)&W1s[d * 64 + c0];
#pragma unroll
            for (int u = 0; u < 8; u++) {
                ull ad = dup2(xi[(r0 + u) * 64 + d]);
                fma2(a0[u][0], ad, wv.x);
                fma2(a0[u][1], ad, wv.y);
            }
        }
#pragma unroll
        for (int u = 0; u < 8; u++) {
            float2 p0 = unpk(a0[u][0]), p1 = unpk(a0[u][1]);
            u32 h0, l0, h1, l1;
            split2(p0.x, p0.y, h0, l0);
            split2(p1.x, p1.y, h1, l1);
            u32 off = (u32)(r0 + u) * 144 + (u32)c0 * 2;
            *(uint2*)(SB + E1H + off) = make_uint2(h0, h1);
            *(uint2*)(SB + E1L + off) = make_uint2(l0, l1);
        }
    }
    __syncthreads();  // staging reads done; E1 visible

    // g3: E2(0) -> buf0, g4: E2(1) -> buf1
    cp_tile(sb + E2B, g_e2h + tb * 8192, tid);
    cp_tile(sb + E2B + 9216, g_e2l + tb * 8192, tid);
    cp_commit();
    cp_tile(sb + E2B + 18432, g_e2h + (tb + 1) * 8192, tid);
    cp_tile(sb + E2B + 18432 + 9216, g_e2l + (tb + 1) * 8192, tid);
    cp_commit();

    // ---- resident E1 A-fragments (rows w*16..w*16+15) ----
    u32 ah[4][4], al[4][4];
    {
        u32 arow = (u32)(w * 16 + (l & 7) + ((l >> 3) & 1) * 8);
        u32 acol = ((u32)(l >> 4)) * 16;
#pragma unroll
        for (int kc = 0; kc < 4; kc++) {
            ldm4(sb + E1H + arow * 144 + kc * 32 + acol,
                 ah[kc][0], ah[kc][1], ah[kc][2], ah[kc][3]);
            ldm4(sb + E1L + arow * 144 + kc * 32 + acol,
                 al[kc][0], al[kc][1], al[kc][2], al[kc][3]);
        }
    }
    cp_wait<1>();
    __syncthreads();  // XT0, XT1, E2(0) ready

    const u32 brl = (u32)((l & 7) * 144 + ((l >> 3) & 1) * 16);
    const u32 bq = (u32)(l >> 4);

    float Hc[8][4];
#pragma unroll
    for (int nb = 0; nb < 8; nb++)
#pragma unroll
        for (int v = 0; v < 4; v++) Hc[nb][v] = 0.f;
    float rsg = 0.f, rsg8 = 0.f;

    for (int jt = 0; jt < 8; jt++) {
        const u32 e2b = sb + E2B + (u32)(jt & 1) * 18432;
        const u32 xtb = sb + XTB + (u32)(jt & 1) * 18432;

        // ---- GEMM1: S = E1 E2^T (3-term split) ----
        float S[8][4];
#pragma unroll
        for (int nb = 0; nb < 8; nb++)
#pragma unroll
            for (int v = 0; v < 4; v++) S[nb][v] = 0.f;
#pragma unroll
        for (int nbp = 0; nbp < 4; nbp++) {
            u32 ro = ((u32)(2 * nbp) + bq) * 1152 + brl;
#pragma unroll
            for (int kc = 0; kc < 4; kc++) {
                u32 h0, h1, h2, h3, q0, q1, q2, q3;
                ldm4(e2b + ro + kc * 32, h0, h1, h2, h3);
                ldm4(e2b + 9216 + ro + kc * 32, q0, q1, q2, q3);
                mmab(S[2 * nbp], ah[kc], h0, h1);
                mmab(S[2 * nbp], al[kc], h0, h1);
                mmab(S[2 * nbp], ah[kc], q0, q1);
                mmab(S[2 * nbp + 1], ah[kc], h2, h3);
                mmab(S[2 * nbp + 1], al[kc], h2, h3);
                mmab(S[2 * nbp + 1], ah[kc], q2, q3);
            }
        }
        // ---- exp(relu), rowsums, split -> P A-frags (registers only) ----
        u32 pah[4][4], pal[4][4];
#pragma unroll
        for (int nb = 0; nb < 8; nb++) {
            float p0 = __expf(fmaxf(S[nb][0], 0.f)), p1 = __expf(fmaxf(S[nb][1], 0.f));
            float p2 = __expf(fmaxf(S[nb][2], 0.f)), p3 = __expf(fmaxf(S[nb][3], 0.f));
            rsg += p0 + p1;
            rsg8 += p2 + p3;
            int kc = nb >> 1, hf = (nb & 1) * 2;
            split2(p0, p1, pah[kc][hf], pal[kc][hf]);
            split2(p2, p3, pah[kc][hf + 1], pal[kc][hf + 1]);
        }
        // ---- GEMM2: H += P X (3-term split) ----
#pragma unroll
        for (int nbp = 0; nbp < 4; nbp++) {
            u32 ro = ((u32)(2 * nbp) + bq) * 1152 + brl;
#pragma unroll
            for (int kc = 0; kc < 4; kc++) {
                u32 h0, h1, h2, h3, q0, q1, q2, q3;
                ldm4(xtb + ro + kc * 32, h0, h1, h2, h3);
                ldm4(xtb + 9216 + ro + kc * 32, q0, q1, q2, q3);
                mmab(Hc[2 * nbp], pah[kc], h0, h1);
                mmab(Hc[2 * nbp], pal[kc], h0, h1);
                mmab(Hc[2 * nbp], pah[kc], q0, q1);
                mmab(Hc[2 * nbp + 1], pah[kc], h2, h3);
                mmab(Hc[2 * nbp + 1], pal[kc], h2, h3);
                mmab(Hc[2 * nbp + 1], pah[kc], q2, q3);
            }
        }
        __syncthreads();  // all warps done reading bufs (jt&1)

        if (jt + 2 < 8) {
            u32 dE = sb + E2B + (u32)(jt & 1) * 18432;
            u32 dX = sb + XTB + (u32)(jt & 1) * 18432;
            cp_tile(dE, g_e2h + (tb + jt + 2) * 8192, tid);
            cp_tile(dE + 9216, g_e2l + (tb + jt + 2) * 8192, tid);
            cp_tile(dX, g_xth + (tb + jt + 2) * 8192, tid);
            cp_tile(dX + 9216, g_xtl + (tb + jt + 2) * 8192, tid);
            cp_commit();
        } else if (jt == 6) {
            float* Wf = (float*)(SB + XTB);  // XT buf0 free after jt=6
#pragma unroll
            for (int i = 0; i < 8; i++) { int ch = tid + 128 * i; cp16(&Wf[ch * 4], &W[ch * 4]); }
            cp_commit();
        }
        cp_wait<1>();
        __syncthreads();
    }

    cp_wait<0>();
    __syncthreads();  // W fp32 resident in XT buf0

    // ---- rowsum reduce (quad lanes share rows) ----
    rsg += __shfl_xor_sync(0xffffffffu, rsg, 1);
    rsg += __shfl_xor_sync(0xffffffffu, rsg, 2);
    rsg8 += __shfl_xor_sync(0xffffffffu, rsg8, 1);
    rsg8 += __shfl_xor_sync(0xffffffffu, rsg8, 2);
    const float ivg = 1.f / rsg, ivg8 = 1.f / rsg8;

    // ---- W^T split planes -> E2 buf0 region ----
    {
        const float* Wf = (const float*)(SB + XTB);
        int h = tid >> 1, dh = (tid & 1) * 32;
        u32 wh[16], wl[16];
#pragma unroll
        for (int c = 0; c < 16; c++) {
            float v0 = Wf[(dh + 2 * c) * 64 + h];
            float v1 = Wf[(dh + 2 * c + 1) * 64 + h];
            split2(v0, v1, wh[c], wl[c]);
        }
        u32 off = (u32)h * 144 + (u32)dh * 2;
#pragma unroll
        for (int c4 = 0; c4 < 4; c4++) {
            *(uint4*)(SB + E2B + off + 16 * c4) = *(uint4*)&wh[4 * c4];
            *(uint4*)(SB + E2B + 9216 + off + 16 * c4) = *(uint4*)&wl[4 * c4];
        }
    }
    __syncthreads();

    // ---- normalize H -> A-frags ----
    u32 hah[4][4], hal[4][4];
#pragma unroll
    for (int nb = 0; nb < 8; nb++) {
        float q0 = Hc[nb][0] * ivg, q1 = Hc[nb][1] * ivg;
        float q2 = Hc[nb][2] * ivg8, q3 = Hc[nb][3] * ivg8;
        int kc = nb >> 1, hf = (nb & 1) * 2;
        split2(q0, q1, hah[kc][hf], hal[kc][hf]);
        split2(q2, q3, hah[kc][hf + 1], hal[kc][hf + 1]);
    }

    // ---- GEMM3: O = H_n W + b (3-term split), bias in C init ----
    const float* bsO = (const float*)(SB + BSO);
    const int tq = l & 3, g = l >> 2;
    float O[8][4];
#pragma unroll
    for (int nb = 0; nb < 8; nb++) {
        float b0 = bsO[nb * 8 + 2 * tq], b1f = bsO[nb * 8 + 2 * tq + 1];
        O[nb][0] = b0; O[nb][1] = b1f; O[nb][2] = b0; O[nb][3] = b1f;
    }
#pragma unroll
    for (int nbp = 0; nbp < 4; nbp++) {
        u32 ro = ((u32)(2 * nbp) + bq) * 1152 + brl;
#pragma unroll
        for (int kc = 0; kc < 4; kc++) {
            u32 h0, h1, h2, h3, q0, q1, q2, q3;
            ldm4(sb + E2B + ro + kc * 32, h0, h1, h2, h3);
            ldm4(sb + E2B + 9216 + ro + kc * 32, q0, q1, q2, q3);
            mmab(O[2 * nbp], hah[kc], h0, h1);
            mmab(O[2 * nbp], hal[kc], h0, h1);
            mmab(O[2 * nbp], hah[kc], q0, q1);
            mmab(O[2 * nbp + 1], hah[kc], h2, h3);
            mmab(O[2 * nbp + 1], hal[kc], h2, h3);
            mmab(O[2 * nbp + 1], hah[kc], q2, q3);
        }
    }
    // ---- store (D-frag rows g, g+8) ----
    {
        int rg = i0 + w * 16 + g;
        float* o0 = out + ((size_t)(b * Nn + rg) * Tt + t) * Hh;
        float* o1 = o0 + (size_t)8 * Tt * Hh;
#pragma unroll
        for (int nb = 0; nb < 8; nb++) {
            int col = nb * 8 + 2 * tq;
            float2 v0 = make_float2(fmaxf(O[nb][0], 0.f), fmaxf(O[nb][1], 0.f));
            float2 v1 = make_float2(fmaxf(O[nb][2], 0.f), fmaxf(O[nb][3], 0.f));
            *(float2*)&o0[col] = v0;
            *(float2*)&o1[col] = v1;
        }
    }
}

// ============================================================================
extern "C" void kernel_launch(void* const* d_in, const int* in_sizes, int n_in,
                              void* d_out, int out_size) {
    const float* x  = (const float*)d_in[0];
    const float* W1 = (const float*)d_in[1];
    const float* b1 = (const float*)d_in[2];
    const float* W2 = (const float*)d_in[3];
    const float* b2 = (const float*)d_in[4];
    const float* W  = (const float*)d_in[5];
    const float* bias = (const float*)d_in[6];
    float* out = (float*)d_out;

    const int smemP = 8512 * 4;   // 34,048 B
    const int smemM = 92672;      // bytes
    cudaFuncSetAttribute(gcn_proj, cudaFuncAttributeMaxDynamicSharedMemorySize, smemP);
    cudaFuncSetAttribute(gcn_main, cudaFuncAttributeMaxDynamicSharedMemorySize, smemM);

    gcn_proj<<<Bb * Tt * 8, 128, smemP>>>(x, W2, b2);
    gcn_main<<<Bb * Tt * 8, 128, smemM>>>(x, W1, b1, W, bias, out);
}